// round 13
// baseline (speedup 1.0000x reference)
#include <cuda_runtime.h>
#include <cuda_bf16.h>
#include <cstdint>
#include <cstddef>

#define B_  256
#define T_  512
#define E_  200
#define H_  100
#define G3_ 300
#define NC_ 5
#define NT_ 100000
#define KP_ 208          // padded K (E_ -> 208)
#define NP_ 320          // padded N (G3_ -> 320)

typedef unsigned long long ull;

// scratch: GRU input preactivations
__device__ float g_xp[39321600];
// pre-converted bf16 hi/lo operands + per-vocab-row norm scales
__device__ __nv_bfloat16 g_embHi[NT_ * E_];
__device__ __nv_bfloat16 g_embLo[NT_ * E_];
__device__ float         g_scale[NT_];
__device__ __nv_bfloat16 g_wHi[NP_ * KP_];
__device__ __nv_bfloat16 g_wLo[NP_ * KP_];

#define FMA2(d, a, b, c) \
    asm("fma.rn.f32x2 %0, %1, %2, %3;" : "=l"(d) : "l"(a), "l"(b), "l"(c))
#define ADD2(d, a, b) \
    asm("add.rn.f32x2 %0, %1, %2;" : "=l"(d) : "l"(a), "l"(b))

__device__ __forceinline__ float sigmoidf_(float x) {
    return 1.0f / (1.0f + __expf(-x));
}
__device__ __forceinline__ float sum2(ull v) {
    float a, b_;
    asm("mov.b64 {%0, %1}, %2;" : "=f"(a), "=f"(b_) : "l"(v));
    return a + b_;
}
__device__ __forceinline__ uint32_t s2u(const void* p) {
    return (uint32_t)__cvta_generic_to_shared(p);
}

#define MMA_BF16(c, a0, a1, a2, a3, b0, b1) \
    asm volatile("mma.sync.aligned.m16n8k16.row.col.f32.bf16.bf16.f32 " \
        "{%0,%1,%2,%3}, {%4,%5,%6,%7}, {%8,%9}, {%0,%1,%2,%3};" \
        : "+f"((c)[0]), "+f"((c)[1]), "+f"((c)[2]), "+f"((c)[3]) \
        : "r"(a0), "r"(a1), "r"(a2), "r"(a3), "r"(b0), "r"(b1))

__device__ __forceinline__ uint32_t pack_bf2(__nv_bfloat16 a, __nv_bfloat16 b) {
    __nv_bfloat162 t; t.x = a; t.y = b;
    return *(uint32_t*)&t;
}

// ---------------------------------------------------------------------------
// Precompute kernels (memory-bound, run once per launch)
// ---------------------------------------------------------------------------
__global__ void __launch_bounds__(256) cvt_emb_kernel(const float* __restrict__ emb)
{
    int idx = blockIdx.x * 256 + threadIdx.x;
    if (idx >= NT_ * E_ / 4) return;
    float4 v = *(const float4*)(emb + (size_t)idx * 4);
    __nv_bfloat16 h0 = __float2bfloat16(v.x), h1 = __float2bfloat16(v.y);
    __nv_bfloat16 h2 = __float2bfloat16(v.z), h3 = __float2bfloat16(v.w);
    __nv_bfloat16 l0 = __float2bfloat16(v.x - __bfloat162float(h0));
    __nv_bfloat16 l1 = __float2bfloat16(v.y - __bfloat162float(h1));
    __nv_bfloat16 l2 = __float2bfloat16(v.z - __bfloat162float(h2));
    __nv_bfloat16 l3 = __float2bfloat16(v.w - __bfloat162float(h3));
    uint2 hi, lo;
    hi.x = pack_bf2(h0, h1); hi.y = pack_bf2(h2, h3);
    lo.x = pack_bf2(l0, l1); lo.y = pack_bf2(l2, l3);
    *(uint2*)(g_embHi + (size_t)idx * 4) = hi;
    *(uint2*)(g_embLo + (size_t)idx * 4) = lo;
}

__global__ void __launch_bounds__(256) norm_kernel(const float* __restrict__ emb)
{
    int warp = (blockIdx.x * 256 + threadIdx.x) >> 5;
    int lane = threadIdx.x & 31;
    if (warp >= NT_) return;
    const float* row = emb + (size_t)warp * E_;
    float p = 0.f;
    for (int k = lane; k < E_; k += 32) { float v = row[k]; p = fmaf(v, v, p); }
    #pragma unroll
    for (int o = 16; o > 0; o >>= 1) p += __shfl_xor_sync(0xffffffffu, p, o);
    if (lane == 0) {
        float n = sqrtf(p);
        g_scale[warp] = (n > 1.0f) ? 1.0f / (n + 1e-7f) : 1.0f;
    }
}

__global__ void __launch_bounds__(256) cvt_w_kernel(const float* __restrict__ W_ih)
{
    int idx = blockIdx.x * 256 + threadIdx.x;
    if (idx >= NP_ * KP_) return;
    int n = idx / KP_, k = idx - n * KP_;
    float v = (n < G3_ && k < E_) ? W_ih[n * E_ + k] : 0.f;
    __nv_bfloat16 h = __float2bfloat16(v);
    __nv_bfloat16 l = __float2bfloat16(v - __bfloat162float(h));
    g_wHi[idx] = h;
    g_wLo[idx] = l;
}

// ---------------------------------------------------------------------------
// Kernel A (mma.sync bf16, pre-converted operands) — unchanged from R12.
// ---------------------------------------------------------------------------
#define A_STRIDE 72
#define A_OFF_TOK  0
#define A_OFF_SC   512
#define A_OFF_EHI  1024
#define A_OFF_ELO  (A_OFF_EHI + 18432)
#define A_OFF_WHI  (A_OFF_ELO + 18432)
#define A_OFF_WLO  (A_OFF_WHI + 23040)
#define A_SMEM_BYTES (A_OFF_WLO + 23040)

__global__ void __launch_bounds__(256) xp_kernel(
    const int* __restrict__ txt, const float* __restrict__ b_ih)
{
    extern __shared__ char smp[];
    int*   toks = (int*)  (smp + A_OFF_TOK);
    float* scs  = (float*)(smp + A_OFF_SC);
    __nv_bfloat16* eHi = (__nv_bfloat16*)(smp + A_OFF_EHI);
    __nv_bfloat16* eLo = (__nv_bfloat16*)(smp + A_OFF_ELO);
    __nv_bfloat16* wHi = (__nv_bfloat16*)(smp + A_OFF_WHI);
    __nv_bfloat16* wLo = (__nv_bfloat16*)(smp + A_OFF_WLO);

    const int tid  = threadIdx.x;
    const int lane = tid & 31;
    const int warp = tid >> 5;
    const int wr   = warp >> 1;
    const int wc   = warp & 1;
    const int g    = lane >> 2;
    const int t4   = lane & 3;
    const int row0 = (blockIdx.x >> 1) * 128;
    const int nh   = blockIdx.x & 1;
    const int col0 = nh * 160;

    if (tid < 128) {
        int tk = txt[row0 + tid];
        toks[tid] = tk;
        scs[tid]  = g_scale[tk];
    }
    __syncthreads();

    float acc[2][10][4];
    #pragma unroll
    for (int mt = 0; mt < 2; mt++)
        #pragma unroll
        for (int nt = 0; nt < 10; nt++)
            #pragma unroll
            for (int q = 0; q < 4; q++) acc[mt][nt][q] = 0.f;

    const int k0s[4]     = {0, 64, 128, 192};
    const int kshifts[4] = {6, 6, 6, 4};

    for (int ch = 0; ch < 4; ++ch) {
        const int k0 = k0s[ch], ksh = kshifts[ch];
        const int klen = 1 << ksh;
        const int c32n = klen >> 1;

        for (int idx = tid; idx < 128 * c32n; idx += 256) {
            int r = idx / c32n, c = idx - r * c32n;
            int k = k0 + 2 * c;
            uint32_t vh = 0, vl = 0;
            if (k < E_) {
                size_t off = (size_t)toks[r] * E_ + k;
                vh = *(const uint32_t*)(g_embHi + off);
                vl = *(const uint32_t*)(g_embLo + off);
            }
            *(uint32_t*)&eHi[r * A_STRIDE + 2 * c] = vh;
            *(uint32_t*)&eLo[r * A_STRIDE + 2 * c] = vl;
        }
        for (int idx = tid; idx < 160 * c32n; idx += 256) {
            int r = idx / c32n, c = idx - r * c32n;
            size_t off = (size_t)(col0 + r) * KP_ + k0 + 2 * c;
            *(uint32_t*)&wHi[r * A_STRIDE + 2 * c] = *(const uint32_t*)(g_wHi + off);
            *(uint32_t*)&wLo[r * A_STRIDE + 2 * c] = *(const uint32_t*)(g_wLo + off);
        }
        __syncthreads();

        const int ksteps = klen >> 4;
        for (int ks = 0; ks < ksteps; ++ks) {
            const int kb = ks * 16 + 2 * t4;
            uint32_t aH[2][4], aL[2][4];
            #pragma unroll
            for (int mt = 0; mt < 2; mt++) {
                int rA = (wr * 32 + mt * 16 + g) * A_STRIDE + kb;
                aH[mt][0] = *(const uint32_t*)&eHi[rA];
                aH[mt][1] = *(const uint32_t*)&eHi[rA + 8 * A_STRIDE];
                aH[mt][2] = *(const uint32_t*)&eHi[rA + 8];
                aH[mt][3] = *(const uint32_t*)&eHi[rA + 8 * A_STRIDE + 8];
                aL[mt][0] = *(const uint32_t*)&eLo[rA];
                aL[mt][1] = *(const uint32_t*)&eLo[rA + 8 * A_STRIDE];
                aL[mt][2] = *(const uint32_t*)&eLo[rA + 8];
                aL[mt][3] = *(const uint32_t*)&eLo[rA + 8 * A_STRIDE + 8];
            }
            #pragma unroll
            for (int nt = 0; nt < 10; nt++) {
                int nb = (wc * 80 + nt * 8 + g) * A_STRIDE + kb;
                uint32_t bH0 = *(const uint32_t*)&wHi[nb];
                uint32_t bH1 = *(const uint32_t*)&wHi[nb + 8];
                uint32_t bL0 = *(const uint32_t*)&wLo[nb];
                uint32_t bL1 = *(const uint32_t*)&wLo[nb + 8];
                #pragma unroll
                for (int mt = 0; mt < 2; mt++) {
                    MMA_BF16(acc[mt][nt], aH[mt][0], aH[mt][1], aH[mt][2], aH[mt][3], bH0, bH1);
                    MMA_BF16(acc[mt][nt], aH[mt][0], aH[mt][1], aH[mt][2], aH[mt][3], bL0, bL1);
                    MMA_BF16(acc[mt][nt], aL[mt][0], aL[mt][1], aL[mt][2], aL[mt][3], bH0, bH1);
                }
            }
        }
        if (ch < 3) __syncthreads();
    }

    #pragma unroll
    for (int mt = 0; mt < 2; mt++) {
        #pragma unroll
        for (int nt = 0; nt < 10; nt++) {
            int row = wr * 32 + mt * 16 + g;
            int col = col0 + wc * 80 + nt * 8 + 2 * t4;
            if (col < G3_) {
                float s0 = scs[row], s8 = scs[row + 8];
                float bc0 = __ldg(b_ih + col), bc1 = __ldg(b_ih + col + 1);
                float2 v0, v1;
                v0.x = fmaf(s0, acc[mt][nt][0], bc0);
                v0.y = fmaf(s0, acc[mt][nt][1], bc1);
                v1.x = fmaf(s8, acc[mt][nt][2], bc0);
                v1.y = fmaf(s8, acc[mt][nt][3], bc1);
                *(float2*)&g_xp[(size_t)(row0 + row) * G3_ + col] = v0;
                *(float2*)&g_xp[(size_t)(row0 + row + 8) * G3_ + col] = v1;
            }
        }
    }
}

// ---------------------------------------------------------------------------
// Kernel B: fused scan. wA rows in registers, wB rows in SMEM (frees ~100
// regs/thread so ptxas can software-pipeline the LDS stream).
// wB layout [252][100] floats: stride 100 ≡ 4 mod 32 banks -> LDS.128
// conflict-free per quarter-warp phase.
// ---------------------------------------------------------------------------
#define SB_WBS   0        // 25200 floats (252 x 100)
#define SB_HS0   25200
#define SB_HS1   25300
#define SB_SS0   25400
#define SB_SS1   25500
#define SB_HP0   25600
#define SB_HP1   25900
#define SB_TIV0  26200
#define SB_TIV1  26300
#define SB_TSS0  26400
#define SB_TSS1  26500
#define SB_SCAL0 26600
#define SB_SCAL1 26604
#define SB_DUM   26608
#define SCAN_SMEM_FLOATS 26616
#define SCAN_SMEM_BYTES  (SCAN_SMEM_FLOATS * 4)

__global__ void __launch_bounds__(256) scan_kernel(
    const int*   __restrict__ lens,
    const float* __restrict__ W_hh, const float* __restrict__ b_hh,
    const float* __restrict__ W_lgr, const float* __restrict__ b_lgr,
    const float* __restrict__ W_ts, const float* __restrict__ b_ts,
    const float* __restrict__ W_ti, const float* __restrict__ b_ti,
    const float* __restrict__ W_out, const float* __restrict__ b_out,
    float* __restrict__ out)
{
    extern __shared__ float sm[];
    float* wBs  = sm + SB_WBS;
    float* hs0  = sm + SB_HS0;   float* hs1  = sm + SB_HS1;
    float* ss0  = sm + SB_SS0;   float* ss1  = sm + SB_SS1;
    float* hp0  = sm + SB_HP0;   float* hp1  = sm + SB_HP1;
    float* tiv0 = sm + SB_TIV0;  float* tiv1 = sm + SB_TIV1;
    float* tss0 = sm + SB_TSS0;  float* tss1 = sm + SB_TSS1;
    float* scal0= sm + SB_SCAL0; float* scal1= sm + SB_SCAL1;
    float* dummy= sm + SB_DUM;

    const int tid = threadIdx.x;
    const int b0  = blockIdx.x * 2;

    int   mode  = 2;                 // 0: dot, 1: sumsq, 2: idle
    int   hhRow = 0;
    const float* wpA = W_hh;
    int   fromMem = 1;
    float wBconst = 0.f;
    float biasA = 0.f, biasB = 0.f;
    uint32_t v0  = s2u(hs0), v1  = s2u(hs1);
    uint32_t oA0 = s2u(dummy), oB0 = s2u(dummy + 1);
    uint32_t oA1 = s2u(dummy + 2), oB1 = s2u(dummy + 3);

    const int r = 2 * tid;
    if (tid < 150) {
        mode = 0; hhRow = 1;
        wpA = W_hh + (size_t)r * 100;
        biasA = b_hh[r]; biasB = b_hh[r + 1];
        v0 = s2u(hs0); v1 = s2u(hs1);
        oA0 = s2u(hp0 + r); oB0 = s2u(hp0 + r + 1);
        oA1 = s2u(hp1 + r); oB1 = s2u(hp1 + r + 1);
    } else if (tid < 200) {
        mode = 0;
        wpA = W_ti + (size_t)(r - 300) * 100;
        v0 = s2u(hs0); v1 = s2u(hs1);
        oA0 = s2u(tiv0 + (r - 300)); oB0 = s2u(tiv0 + (r - 299));
        oA1 = s2u(tiv1 + (r - 300)); oB1 = s2u(tiv1 + (r - 299));
    } else if (tid < 250) {
        mode = 0;
        wpA = W_ts + (size_t)(r - 400) * 100;
        v0 = s2u(ss0); v1 = s2u(ss1);
        oA0 = s2u(tss0 + (r - 400)); oB0 = s2u(tss0 + (r - 399));
        oA1 = s2u(tss1 + (r - 400)); oB1 = s2u(tss1 + (r - 399));
    } else if (tid == 250) {
        mode = 0;
        wpA = W_lgr;
        fromMem = 0; wBconst = 1.0f;
        v0 = s2u(hs0); v1 = s2u(hs1);
        oA0 = s2u(scal0 + 2); oB0 = s2u(scal0 + 0);
        oA1 = s2u(scal1 + 2); oB1 = s2u(scal1 + 0);
    } else if (tid == 251) {
        mode = 0;
        wpA = W_lgr + 100;
        fromMem = 0; wBconst = 0.0f;
        v0 = s2u(ss0); v1 = s2u(ss1);
        oA0 = s2u(scal0 + 3); oB0 = s2u(dummy + 4);
        oA1 = s2u(scal1 + 3); oB1 = s2u(dummy + 5);
    } else if (tid == 252) {
        mode = 1;
        v0 = s2u(hs0);
        oA0 = s2u(scal0 + 1);
    } else if (tid == 253) {
        mode = 1;
        v0 = s2u(hs1);
        oA0 = s2u(scal1 + 1);
    }

    // wA rows -> registers; wB rows -> SMEM
    ull wA[50];
    {
        const ull* a = (const ull*)wpA;
        #pragma unroll
        for (int i = 0; i < 50; i++) wA[i] = a[i];
    }
    if (tid < 252) {
        float* dst = wBs + tid * 100;
        if (fromMem) {
            const float* src = wpA + 100;
            #pragma unroll
            for (int i = 0; i < 25; i++)
                *(float4*)(dst + 4 * i) = *(const float4*)(src + 4 * i);
        } else {
            #pragma unroll
            for (int i = 0; i < 100; i++) dst[i] = wBconst;
        }
    }
    const uint32_t wboff = s2u(wBs + tid * 100);

    const int batch = (tid >= 100);
    const int ei    = tid - 100 * batch;
    float hreg = 0.f, sreg = 0.f;
    if (tid < 100) { hs0[tid] = 0.f; hs1[tid] = 0.f; ss0[tid] = 0.f; ss1[tid] = 0.f; }

    float bti = 0.f, bts = 0.f;
    int   len = 0;
    const float* xpb = g_xp;
    float* hsP = hs0; float* ssP = ss0;
    const float* hpP = hp0; const float* tivP = tiv0; const float* tssP = tss0;
    const float* scalP = scal0;
    if (tid < 200) {
        bti = b_ti[ei]; bts = b_ts[ei];
        len = lens[b0 + batch];
        xpb = g_xp + (size_t)(b0 + batch) * T_ * G3_;
        if (batch) { hsP = hs1; ssP = ss1; hpP = hp1; tivP = tiv1; tssP = tss1; scalP = scal1; }
    }
    const float blgr = b_lgr[0];

    float xv0 = 0.f, xv1 = 0.f, xv2 = 0.f;
    float xn0 = 0.f, xn1 = 0.f, xn2 = 0.f;
    if (tid < 200) {
        xv0 = xpb[ei]; xv1 = xpb[100 + ei]; xv2 = xpb[200 + ei];
    }
    __syncthreads();

    for (int t = 0; t <= T_; ++t) {
        // ---------------- Stage 1 ----------------
        if (tid < 200 && t + 1 < T_) {
            const float* x = xpb + (size_t)(t + 1) * G3_;
            xn0 = x[ei]; xn1 = x[100 + ei]; xn2 = x[200 + ei];
        }

        const bool act = (mode == 0) ? (hhRow ? (t < T_) : (t >= 1))
                                     : (mode == 1 && t >= 1);
        if (mode == 0 && act) {
            ull a0 = 0ull, a1 = 0ull, bb0 = 0ull, bb1 = 0ull;
            ull c0 = 0ull, c1 = 0ull, d0 = 0ull, d1 = 0ull;
            #pragma unroll
            for (int i = 0; i < 25; i++) {
                ull hx0, hy0, hx1, hy1, wb0, wb1;
                asm volatile("ld.shared.v2.b64 {%0, %1}, [%2];"
                             : "=l"(hx0), "=l"(hy0) : "r"(v0 + i * 16));
                asm volatile("ld.shared.v2.b64 {%0, %1}, [%2];"
                             : "=l"(hx1), "=l"(hy1) : "r"(v1 + i * 16));
                asm volatile("ld.shared.v2.b64 {%0, %1}, [%2];"
                             : "=l"(wb0), "=l"(wb1) : "r"(wboff + i * 16));
                FMA2(a0,  wA[2 * i],     hx0, a0);
                FMA2(a1,  wA[2 * i + 1], hy0, a1);
                FMA2(bb0, wb0,           hx0, bb0);
                FMA2(bb1, wb1,           hy0, bb1);
                FMA2(c0,  wA[2 * i],     hx1, c0);
                FMA2(c1,  wA[2 * i + 1], hy1, c1);
                FMA2(d0,  wb0,           hx1, d0);
                FMA2(d1,  wb1,           hy1, d1);
            }
            ull ta, tb, tc, td;
            ADD2(ta, a0, a1);
            ADD2(tb, bb0, bb1);
            ADD2(tc, c0, c1);
            ADD2(td, d0, d1);
            float rA0 = sum2(ta) + biasA;
            float rB0 = sum2(tb) + biasB;
            float rA1 = sum2(tc) + biasA;
            float rB1 = sum2(td) + biasB;
            asm volatile("st.shared.f32 [%0], %1;" :: "r"(oA0), "f"(rA0));
            asm volatile("st.shared.f32 [%0], %1;" :: "r"(oB0), "f"(rB0));
            asm volatile("st.shared.f32 [%0], %1;" :: "r"(oA1), "f"(rA1));
            asm volatile("st.shared.f32 [%0], %1;" :: "r"(oB1), "f"(rB1));
        } else if (mode == 1 && act) {
            ull a0 = 0ull, a1 = 0ull;
            #pragma unroll
            for (int i = 0; i < 25; i++) {
                ull hx, hy;
                asm volatile("ld.shared.v2.b64 {%0, %1}, [%2];"
                             : "=l"(hx), "=l"(hy) : "r"(v0 + i * 16));
                FMA2(a0, hx, hx, a0);
                FMA2(a1, hy, hy, a1);
            }
            ull ta;
            ADD2(ta, a0, a1);
            float rA = sum2(ta);
            asm volatile("st.shared.f32 [%0], %1;" :: "r"(oA0), "f"(rA));
        }
        __syncthreads();

        // ---------------- Stage 2 ----------------
        if (tid < 200) {
            if (t < T_) {
                float rr = sigmoidf_(xv0 + hpP[ei]);
                float z  = sigmoidf_(xv1 + hpP[100 + ei]);
                float ng = tanhf    (xv2 + rr * hpP[200 + ei]);
                hreg = (1.f - z) * ng + z * hreg;
                hsP[ei] = hreg;
                xv0 = xn0; xv1 = xn1; xv2 = xn2;
            }
            if (t >= 1) {
                float hsum = scalP[0], h2 = scalP[1], li = scalP[2], wd = scalP[3];
                float att  = 0.001f * hsum / fmaxf(sqrtf(h2), 1e-12f);
                float zt   = (t - 1 < len) ? fmaxf(att, 0.f) : 0.f;
                float gate = sigmoidf_(li + wd + blgr);
                float ns   = tanhf(tivP[ei] + bti + gate * tssP[ei] + bts);
                sreg = (1.f - zt) * sreg + zt * ns;
                ssP[ei] = sreg;
            }
        }
        __syncthreads();
    }

    if (tid < NC_) {
        float a = b_out[tid];
        for (int k = 0; k < 100; ++k)
            a = fmaf(W_out[tid * 100 + k], ss0[k], a);
        out[b0 * NC_ + tid] = a;
    } else if (tid >= 32 && tid < 32 + NC_) {
        int c = tid - 32;
        float a = b_out[c];
        for (int k = 0; k < 100; ++k)
            a = fmaf(W_out[c * 100 + k], ss1[k], a);
        out[(b0 + 1) * NC_ + c] = a;
    }
}

extern "C" void kernel_launch(void* const* d_in, const int* in_sizes, int n_in,
                              void* d_out, int out_size)
{
    const int*   txt   = (const int*)  d_in[0];
    const int*   lens  = (const int*)  d_in[1];
    const float* emb   = (const float*)d_in[2];
    const float* W_ih  = (const float*)d_in[3];
    const float* W_hh  = (const float*)d_in[4];
    const float* b_ih  = (const float*)d_in[5];
    const float* b_hh  = (const float*)d_in[6];
    const float* W_lgr = (const float*)d_in[7];
    const float* b_lgr = (const float*)d_in[8];
    const float* W_ts  = (const float*)d_in[9];
    const float* b_ts  = (const float*)d_in[10];
    const float* W_ti  = (const float*)d_in[11];
    const float* b_ti  = (const float*)d_in[12];
    const float* W_out = (const float*)d_in[13];
    const float* b_out = (const float*)d_in[14];
    float* out = (float*)d_out;

    cudaFuncSetAttribute(xp_kernel,
                         cudaFuncAttributeMaxDynamicSharedMemorySize,
                         A_SMEM_BYTES);
    cudaFuncSetAttribute(scan_kernel,
                         cudaFuncAttributeMaxDynamicSharedMemorySize,
                         SCAN_SMEM_BYTES);

    cvt_emb_kernel<<<(NT_ * E_ / 4 + 255) / 256, 256>>>(emb);
    norm_kernel<<<(NT_ * 32 + 255) / 256, 256>>>(emb);
    cvt_w_kernel<<<(NP_ * KP_ + 255) / 256, 256>>>(W_ih);

    xp_kernel<<<(B_ * T_ / 128) * 2, 256, A_SMEM_BYTES>>>(txt, b_ih);
    scan_kernel<<<B_ / 2, 256, SCAN_SMEM_BYTES>>>(lens,
                                 W_hh, b_hh, W_lgr, b_lgr,
                                 W_ts, b_ts, W_ti, b_ti,
                                 W_out, b_out, out);
}

// round 14
// speedup vs baseline: 1.0343x; 1.0343x over previous
#include <cuda_runtime.h>
#include <cuda_bf16.h>
#include <cstdint>
#include <cstddef>

#define B_  256
#define T_  512
#define E_  200
#define H_  100
#define G3_ 300
#define NC_ 5
#define NT_ 100000
#define KP_ 208
#define NP_ 320

typedef unsigned long long ull;

__device__ float g_xp[39321600];
__device__ __nv_bfloat16 g_embHi[NT_ * E_];
__device__ __nv_bfloat16 g_embLo[NT_ * E_];
__device__ float         g_scale[NT_];
__device__ __nv_bfloat16 g_wHi[NP_ * KP_];
__device__ __nv_bfloat16 g_wLo[NP_ * KP_];
// scan stage-1 combined weight matrix: rows 0-299 W_hh, 300-399 W_ti,
// 400-499 W_ts, 500-511 zero; cols 0-99 real, 100-111 zero. bf16 hi/lo.
__device__ __nv_bfloat16 g_wsHi[512 * 112];
__device__ __nv_bfloat16 g_wsLo[512 * 112];

__device__ __forceinline__ float sigmoidf_(float x) {
    return 1.0f / (1.0f + __expf(-x));
}
__device__ __forceinline__ uint32_t s2u(const void* p) {
    return (uint32_t)__cvta_generic_to_shared(p);
}

#define MMA_BF16(c, a0, a1, a2, a3, b0, b1) \
    asm volatile("mma.sync.aligned.m16n8k16.row.col.f32.bf16.bf16.f32 " \
        "{%0,%1,%2,%3}, {%4,%5,%6,%7}, {%8,%9}, {%0,%1,%2,%3};" \
        : "+f"((c)[0]), "+f"((c)[1]), "+f"((c)[2]), "+f"((c)[3]) \
        : "r"(a0), "r"(a1), "r"(a2), "r"(a3), "r"(b0), "r"(b1))

__device__ __forceinline__ uint32_t pack_bf2(__nv_bfloat16 a, __nv_bfloat16 b) {
    __nv_bfloat162 t; t.x = a; t.y = b;
    return *(uint32_t*)&t;
}

// ---------------------------------------------------------------------------
// Precompute kernels
// ---------------------------------------------------------------------------
__global__ void __launch_bounds__(256) cvt_emb_kernel(const float* __restrict__ emb)
{
    int idx = blockIdx.x * 256 + threadIdx.x;
    if (idx >= NT_ * E_ / 4) return;
    float4 v = *(const float4*)(emb + (size_t)idx * 4);
    __nv_bfloat16 h0 = __float2bfloat16(v.x), h1 = __float2bfloat16(v.y);
    __nv_bfloat16 h2 = __float2bfloat16(v.z), h3 = __float2bfloat16(v.w);
    __nv_bfloat16 l0 = __float2bfloat16(v.x - __bfloat162float(h0));
    __nv_bfloat16 l1 = __float2bfloat16(v.y - __bfloat162float(h1));
    __nv_bfloat16 l2 = __float2bfloat16(v.z - __bfloat162float(h2));
    __nv_bfloat16 l3 = __float2bfloat16(v.w - __bfloat162float(h3));
    uint2 hi, lo;
    hi.x = pack_bf2(h0, h1); hi.y = pack_bf2(h2, h3);
    lo.x = pack_bf2(l0, l1); lo.y = pack_bf2(l2, l3);
    *(uint2*)(g_embHi + (size_t)idx * 4) = hi;
    *(uint2*)(g_embLo + (size_t)idx * 4) = lo;
}

__global__ void __launch_bounds__(256) norm_kernel(const float* __restrict__ emb)
{
    int warp = (blockIdx.x * 256 + threadIdx.x) >> 5;
    int lane = threadIdx.x & 31;
    if (warp >= NT_) return;
    const float* row = emb + (size_t)warp * E_;
    float p = 0.f;
    for (int k = lane; k < E_; k += 32) { float v = row[k]; p = fmaf(v, v, p); }
    #pragma unroll
    for (int o = 16; o > 0; o >>= 1) p += __shfl_xor_sync(0xffffffffu, p, o);
    if (lane == 0) {
        float n = sqrtf(p);
        g_scale[warp] = (n > 1.0f) ? 1.0f / (n + 1e-7f) : 1.0f;
    }
}

__global__ void __launch_bounds__(256) cvt_w_kernel(const float* __restrict__ W_ih)
{
    int idx = blockIdx.x * 256 + threadIdx.x;
    if (idx >= NP_ * KP_) return;
    int n = idx / KP_, k = idx - n * KP_;
    float v = (n < G3_ && k < E_) ? W_ih[n * E_ + k] : 0.f;
    __nv_bfloat16 h = __float2bfloat16(v);
    g_wHi[idx] = h;
    g_wLo[idx] = __float2bfloat16(v - __bfloat162float(h));
}

__global__ void __launch_bounds__(256) cvt_ws_kernel(
    const float* __restrict__ W_hh, const float* __restrict__ W_ti,
    const float* __restrict__ W_ts)
{
    int idx = blockIdx.x * 256 + threadIdx.x;
    if (idx >= 512 * 112) return;
    int row = idx / 112, k = idx - row * 112;
    float v = 0.f;
    if (k < H_) {
        if (row < 300)      v = W_hh[row * H_ + k];
        else if (row < 400) v = W_ti[(row - 300) * H_ + k];
        else if (row < 500) v = W_ts[(row - 400) * H_ + k];
    }
    __nv_bfloat16 h = __float2bfloat16(v);
    g_wsHi[idx] = h;
    g_wsLo[idx] = __float2bfloat16(v - __bfloat162float(h));
}

// ---------------------------------------------------------------------------
// Kernel A (mma.sync bf16, pre-converted operands) — unchanged from R12.
// ---------------------------------------------------------------------------
#define A_STRIDE 72
#define A_OFF_TOK  0
#define A_OFF_SC   512
#define A_OFF_EHI  1024
#define A_OFF_ELO  (A_OFF_EHI + 18432)
#define A_OFF_WHI  (A_OFF_ELO + 18432)
#define A_OFF_WLO  (A_OFF_WHI + 23040)
#define A_SMEM_BYTES (A_OFF_WLO + 23040)

__global__ void __launch_bounds__(256) xp_kernel(
    const int* __restrict__ txt, const float* __restrict__ b_ih)
{
    extern __shared__ char smp[];
    int*   toks = (int*)  (smp + A_OFF_TOK);
    float* scs  = (float*)(smp + A_OFF_SC);
    __nv_bfloat16* eHi = (__nv_bfloat16*)(smp + A_OFF_EHI);
    __nv_bfloat16* eLo = (__nv_bfloat16*)(smp + A_OFF_ELO);
    __nv_bfloat16* wHi = (__nv_bfloat16*)(smp + A_OFF_WHI);
    __nv_bfloat16* wLo = (__nv_bfloat16*)(smp + A_OFF_WLO);

    const int tid  = threadIdx.x;
    const int lane = tid & 31;
    const int warp = tid >> 5;
    const int wr   = warp >> 1;
    const int wc   = warp & 1;
    const int g    = lane >> 2;
    const int t4   = lane & 3;
    const int row0 = (blockIdx.x >> 1) * 128;
    const int nh   = blockIdx.x & 1;
    const int col0 = nh * 160;

    if (tid < 128) {
        int tk = txt[row0 + tid];
        toks[tid] = tk;
        scs[tid]  = g_scale[tk];
    }
    __syncthreads();

    float acc[2][10][4];
    #pragma unroll
    for (int mt = 0; mt < 2; mt++)
        #pragma unroll
        for (int nt = 0; nt < 10; nt++)
            #pragma unroll
            for (int q = 0; q < 4; q++) acc[mt][nt][q] = 0.f;

    const int k0s[4]     = {0, 64, 128, 192};
    const int kshifts[4] = {6, 6, 6, 4};

    for (int ch = 0; ch < 4; ++ch) {
        const int k0 = k0s[ch], ksh = kshifts[ch];
        const int klen = 1 << ksh;
        const int c32n = klen >> 1;

        for (int idx = tid; idx < 128 * c32n; idx += 256) {
            int r = idx / c32n, c = idx - r * c32n;
            int k = k0 + 2 * c;
            uint32_t vh = 0, vl = 0;
            if (k < E_) {
                size_t off = (size_t)toks[r] * E_ + k;
                vh = *(const uint32_t*)(g_embHi + off);
                vl = *(const uint32_t*)(g_embLo + off);
            }
            *(uint32_t*)&eHi[r * A_STRIDE + 2 * c] = vh;
            *(uint32_t*)&eLo[r * A_STRIDE + 2 * c] = vl;
        }
        for (int idx = tid; idx < 160 * c32n; idx += 256) {
            int r = idx / c32n, c = idx - r * c32n;
            size_t off = (size_t)(col0 + r) * KP_ + k0 + 2 * c;
            *(uint32_t*)&wHi[r * A_STRIDE + 2 * c] = *(const uint32_t*)(g_wHi + off);
            *(uint32_t*)&wLo[r * A_STRIDE + 2 * c] = *(const uint32_t*)(g_wLo + off);
        }
        __syncthreads();

        const int ksteps = klen >> 4;
        for (int ks = 0; ks < ksteps; ++ks) {
            const int kb = ks * 16 + 2 * t4;
            uint32_t aH[2][4], aL[2][4];
            #pragma unroll
            for (int mt = 0; mt < 2; mt++) {
                int rA = (wr * 32 + mt * 16 + g) * A_STRIDE + kb;
                aH[mt][0] = *(const uint32_t*)&eHi[rA];
                aH[mt][1] = *(const uint32_t*)&eHi[rA + 8 * A_STRIDE];
                aH[mt][2] = *(const uint32_t*)&eHi[rA + 8];
                aH[mt][3] = *(const uint32_t*)&eHi[rA + 8 * A_STRIDE + 8];
                aL[mt][0] = *(const uint32_t*)&eLo[rA];
                aL[mt][1] = *(const uint32_t*)&eLo[rA + 8 * A_STRIDE];
                aL[mt][2] = *(const uint32_t*)&eLo[rA + 8];
                aL[mt][3] = *(const uint32_t*)&eLo[rA + 8 * A_STRIDE + 8];
            }
            #pragma unroll
            for (int nt = 0; nt < 10; nt++) {
                int nb = (wc * 80 + nt * 8 + g) * A_STRIDE + kb;
                uint32_t bH0 = *(const uint32_t*)&wHi[nb];
                uint32_t bH1 = *(const uint32_t*)&wHi[nb + 8];
                uint32_t bL0 = *(const uint32_t*)&wLo[nb];
                uint32_t bL1 = *(const uint32_t*)&wLo[nb + 8];
                #pragma unroll
                for (int mt = 0; mt < 2; mt++) {
                    MMA_BF16(acc[mt][nt], aH[mt][0], aH[mt][1], aH[mt][2], aH[mt][3], bH0, bH1);
                    MMA_BF16(acc[mt][nt], aH[mt][0], aH[mt][1], aH[mt][2], aH[mt][3], bL0, bL1);
                    MMA_BF16(acc[mt][nt], aL[mt][0], aL[mt][1], aL[mt][2], aL[mt][3], bH0, bH1);
                }
            }
        }
        if (ch < 3) __syncthreads();
    }

    #pragma unroll
    for (int mt = 0; mt < 2; mt++) {
        #pragma unroll
        for (int nt = 0; nt < 10; nt++) {
            int row = wr * 32 + mt * 16 + g;
            int col = col0 + wc * 80 + nt * 8 + 2 * t4;
            if (col < G3_) {
                float s0 = scs[row], s8 = scs[row + 8];
                float bc0 = __ldg(b_ih + col), bc1 = __ldg(b_ih + col + 1);
                float2 v0, v1;
                v0.x = fmaf(s0, acc[mt][nt][0], bc0);
                v0.y = fmaf(s0, acc[mt][nt][1], bc1);
                v1.x = fmaf(s8, acc[mt][nt][2], bc0);
                v1.y = fmaf(s8, acc[mt][nt][3], bc1);
                *(float2*)&g_xp[(size_t)(row0 + row) * G3_ + col] = v0;
                *(float2*)&g_xp[(size_t)(row0 + row + 8) * G3_ + col] = v1;
            }
        }
    }
}

// ---------------------------------------------------------------------------
// Kernel B: fused scan with tensor-core stage 1.
// Per iteration t: OUT(512x2) = W_all(512x112) x B(112x2), where
//   B = h_{t-1} for M-tiles 0-24 (rows 0-399), s_{t-2} for tiles 25-31.
// 3-term bf16 split: Whi(regs)*Bhi + Whi*Blo + Wlo(SMEM)*Bhi.
// Stage 2 (tid<200): GRU h-update (t<512) + 2nd-recurrence s-update (t>=1),
// writing fp32 state AND bf16 hi/lo B-operand rows.
// ---------------------------------------------------------------------------
#define SC_WLO    0                    // bf16[512][120] = 122880
#define SC_HBHI   122880               // bf16[8][120] = 1920
#define SC_HBLO   124800
#define SC_SBHI   126720
#define SC_SBLO   128640
#define SC_OUT0   130560               // f32[512] = 2048
#define SC_OUT1   132608
#define SC_BIAS   134656               // f32[512]
#define SC_HS0    136704               // f32[100] x4
#define SC_HS1    137104
#define SC_SS0    137504
#define SC_SS1    137904
#define SC_WLQ    138304
#define SC_WLS    138704
#define SC_SCAL0  139104
#define SC_SCAL1  139120
#define SC_SMEM_BYTES 139136

__global__ void __launch_bounds__(256) scan_kernel(
    const int*   __restrict__ lens,
    const float* __restrict__ b_hh,
    const float* __restrict__ W_lgr, const float* __restrict__ b_lgr,
    const float* __restrict__ b_ts, const float* __restrict__ b_ti,
    const float* __restrict__ W_out, const float* __restrict__ b_out,
    float* __restrict__ out)
{
    extern __shared__ char smc[];
    float* out0 = (float*)(smc + SC_OUT0);
    float* out1 = (float*)(smc + SC_OUT1);
    float* bias = (float*)(smc + SC_BIAS);
    float* hs0  = (float*)(smc + SC_HS0);
    float* hs1  = (float*)(smc + SC_HS1);
    float* ss0  = (float*)(smc + SC_SS0);
    float* ss1  = (float*)(smc + SC_SS1);
    float* wlq  = (float*)(smc + SC_WLQ);
    float* wls  = (float*)(smc + SC_WLS);
    float* scal0= (float*)(smc + SC_SCAL0);
    float* scal1= (float*)(smc + SC_SCAL1);

    const int tid  = threadIdx.x;
    const int lane = tid & 31;
    const int warp = tid >> 5;
    const int g    = lane >> 2;
    const int t4   = lane & 3;
    const int b0g  = blockIdx.x * 2;

    // ---- init staging ----
    // W-lo: [512][120] bf16 rows (cols 112-119 zero pad)
    for (int idx = tid; idx < 512 * 60; idx += 256) {
        int row = idx / 60, c2 = idx - row * 60;
        int col = 2 * c2;
        uint32_t v = 0;
        if (col < 112) v = *(const uint32_t*)(g_wsLo + (size_t)row * 112 + col);
        *(uint32_t*)(smc + SC_WLO + row * 240 + col * 2) = v;
    }
    // zero h/s bf16 operand arrays (8 rows x 120 each x4 arrays)
    for (int idx = tid; idx < 4 * 480; idx += 256)
        *(uint32_t*)(smc + SC_HBHI + idx * 4) = 0;
    for (int idx = tid; idx < 512; idx += 256)
        bias[idx] = (idx < 300) ? b_hh[idx] : 0.f;
    if (tid < 100) {
        wlq[tid] = W_lgr[tid];
        wls[tid] = W_lgr[100 + tid];
        hs0[tid] = 0.f; hs1[tid] = 0.f; ss0[tid] = 0.f; ss1[tid] = 0.f;
    }

    // ---- W-hi fragments -> registers (tiles: warp, warp+8, warp+16, warp+24)
    uint32_t whi[4][7][4];
    #pragma unroll
    for (int j = 0; j < 4; j++) {
        const __nv_bfloat16* tb = g_wsHi
            + (size_t)(16 * (warp + 8 * j) + g) * 112 + 2 * t4;
        #pragma unroll
        for (int ks = 0; ks < 7; ks++) {
            const __nv_bfloat16* p = tb + 16 * ks;
            whi[j][ks][0] = *(const uint32_t*)p;
            whi[j][ks][1] = *(const uint32_t*)(p + 8 * 112);
            whi[j][ks][2] = *(const uint32_t*)(p + 8);
            whi[j][ks][3] = *(const uint32_t*)(p + 8 * 112 + 8);
        }
    }

    // per-thread stage-2 state
    const int batch = (tid >= 100);
    const int ei    = tid - 100 * batch;
    float hreg = 0.f, sreg = 0.f;
    float bti = 0.f, bts = 0.f;
    int   len = 0;
    const float* xpb = g_xp;
    float* hsP = hs0; float* ssP = ss0;
    float* outP = out0; float* scalP = scal0;
    __nv_bfloat16* hbHiP = (__nv_bfloat16*)(smc + SC_HBHI);
    __nv_bfloat16* hbLoP = (__nv_bfloat16*)(smc + SC_HBLO);
    __nv_bfloat16* sbHiP = (__nv_bfloat16*)(smc + SC_SBHI);
    __nv_bfloat16* sbLoP = (__nv_bfloat16*)(smc + SC_SBLO);
    if (tid < 200) {
        bti = b_ti[ei]; bts = b_ts[ei];
        len = lens[b0g + batch];
        xpb = g_xp + (size_t)(b0g + batch) * T_ * G3_;
        if (batch) { hsP = hs1; ssP = ss1; outP = out1; scalP = scal1; }
        hbHiP += batch * 120; hbLoP += batch * 120;
        sbHiP += batch * 120; sbLoP += batch * 120;
    }
    const float blgr = b_lgr[0];

    float xv0 = 0.f, xv1 = 0.f, xv2 = 0.f;
    float xn0 = 0.f, xn1 = 0.f, xn2 = 0.f;
    if (tid < 200) {
        xv0 = xpb[ei]; xv1 = xpb[100 + ei]; xv2 = xpb[200 + ei];
    }

    // B-frag smem byte bases (row g)
    const uint32_t hbHiOff = s2u(smc + SC_HBHI) + g * 240;
    const uint32_t hbLoOff = s2u(smc + SC_HBLO) + g * 240;
    const uint32_t sbHiOff = s2u(smc + SC_SBHI) + g * 240;
    const uint32_t sbLoOff = s2u(smc + SC_SBLO) + g * 240;
    // W-lo A-frag smem bases per tile
    uint32_t aLoBase[4];
    #pragma unroll
    for (int j = 0; j < 4; j++)
        aLoBase[j] = s2u(smc + SC_WLO)
                   + (16 * (warp + 8 * j) + g) * 240 + 4 * t4;

    const int rkind = warp & 3;      // reduction kind
    const int rbat  = warp >> 2;     // reduction batch
    const float* rh = rbat ? hs1 : hs0;
    const float* rs = rbat ? ss1 : ss0;
    float* rscal = rbat ? scal1 : scal0;

    __syncthreads();

    for (int t = 0; t <= T_; ++t) {
        // ================= Stage 1 (tensor) =================
        if (tid < 200 && t + 1 < T_) {
            const float* x = xpb + (size_t)(t + 1) * G3_;
            xn0 = x[ei]; xn1 = x[100 + ei]; xn2 = x[200 + ei];
        }

        float acc[4][4];
        #pragma unroll
        for (int j = 0; j < 4; j++)
            #pragma unroll
            for (int q = 0; q < 4; q++) acc[j][q] = 0.f;

        #pragma unroll
        for (int ks = 0; ks < 7; ks++) {
            const uint32_t kb = 32 * ks + 4 * t4;
            uint32_t bh0h, bh1h, bh0l, bh1l, bs0h, bs1h, bs0l, bs1l;
            asm volatile("ld.shared.b32 %0, [%1];" : "=r"(bh0h) : "r"(hbHiOff + kb));
            asm volatile("ld.shared.b32 %0, [%1];" : "=r"(bh1h) : "r"(hbHiOff + kb + 16));
            asm volatile("ld.shared.b32 %0, [%1];" : "=r"(bh0l) : "r"(hbLoOff + kb));
            asm volatile("ld.shared.b32 %0, [%1];" : "=r"(bh1l) : "r"(hbLoOff + kb + 16));
            asm volatile("ld.shared.b32 %0, [%1];" : "=r"(bs0h) : "r"(sbHiOff + kb));
            asm volatile("ld.shared.b32 %0, [%1];" : "=r"(bs1h) : "r"(sbHiOff + kb + 16));
            asm volatile("ld.shared.b32 %0, [%1];" : "=r"(bs0l) : "r"(sbLoOff + kb));
            asm volatile("ld.shared.b32 %0, [%1];" : "=r"(bs1l) : "r"(sbLoOff + kb + 16));
            #pragma unroll
            for (int j = 0; j < 4; j++) {
                const bool useS = (warp + 8 * j) >= 25;
                uint32_t b0h = useS ? bs0h : bh0h;
                uint32_t b1h = useS ? bs1h : bh1h;
                uint32_t b0l = useS ? bs0l : bh0l;
                uint32_t b1l = useS ? bs1l : bh1l;
                uint32_t al0, al1, al2, al3;
                uint32_t ab = aLoBase[j] + 32 * ks;
                asm volatile("ld.shared.b32 %0, [%1];" : "=r"(al0) : "r"(ab));
                asm volatile("ld.shared.b32 %0, [%1];" : "=r"(al1) : "r"(ab + 1920));
                asm volatile("ld.shared.b32 %0, [%1];" : "=r"(al2) : "r"(ab + 16));
                asm volatile("ld.shared.b32 %0, [%1];" : "=r"(al3) : "r"(ab + 1936));
                MMA_BF16(acc[j], whi[j][ks][0], whi[j][ks][1], whi[j][ks][2], whi[j][ks][3], b0h, b1h);
                MMA_BF16(acc[j], whi[j][ks][0], whi[j][ks][1], whi[j][ks][2], whi[j][ks][3], b0l, b1l);
                MMA_BF16(acc[j], al0, al1, al2, al3, b0h, b1h);
            }
        }

        // store C fragments (lanes t4==0 hold batch cols 0,1)
        if (t4 == 0) {
            #pragma unroll
            for (int j = 0; j < 4; j++) {
                int r0 = 16 * (warp + 8 * j) + g;
                int r1 = r0 + 8;
                if (r0 < 500) {
                    float bb = bias[r0];
                    out0[r0] = acc[j][0] + bb;
                    out1[r0] = acc[j][1] + bb;
                }
                if (r1 < 500) {
                    float bb = bias[r1];
                    out0[r1] = acc[j][2] + bb;
                    out1[r1] = acc[j][3] + bb;
                }
            }
        }

        // scalar reductions (one per warp) on fp32 h_{t-1}/s_{t-2}
        {
            float v;
            if (rkind == 0) {
                v = rh[lane] + rh[lane + 32] + rh[lane + 64]
                  + ((lane < 4) ? rh[lane + 96] : 0.f);
            } else if (rkind == 1) {
                float a = rh[lane], c = rh[lane + 32], d = rh[lane + 64];
                float e = (lane < 4) ? rh[lane + 96] : 0.f;
                v = a * a + c * c + d * d + e * e;
            } else if (rkind == 2) {
                v = wlq[lane] * rh[lane] + wlq[lane + 32] * rh[lane + 32]
                  + wlq[lane + 64] * rh[lane + 64]
                  + ((lane < 4) ? wlq[lane + 96] * rh[lane + 96] : 0.f);
            } else {
                v = wls[lane] * rs[lane] + wls[lane + 32] * rs[lane + 32]
                  + wls[lane + 64] * rs[lane + 64]
                  + ((lane < 4) ? wls[lane + 96] * rs[lane + 96] : 0.f);
            }
            #pragma unroll
            for (int o = 16; o > 0; o >>= 1) v += __shfl_xor_sync(0xffffffffu, v, o);
            if (lane == 0) rscal[rkind] = v;
        }
        __syncthreads();

        // ================= Stage 2 (elementwise) =================
        if (tid < 200) {
            if (t < T_) {
                float rr = sigmoidf_(xv0 + outP[ei]);
                float z  = sigmoidf_(xv1 + outP[100 + ei]);
                float ng = tanhf    (xv2 + rr * outP[200 + ei]);
                hreg = (1.f - z) * ng + z * hreg;
                hsP[ei] = hreg;
                __nv_bfloat16 hh = __float2bfloat16(hreg);
                hbHiP[ei] = hh;
                hbLoP[ei] = __float2bfloat16(hreg - __bfloat162float(hh));
                xv0 = xn0; xv1 = xn1; xv2 = xn2;
            }
            if (t >= 1) {
                float hsum = scalP[0], h2 = scalP[1], li = scalP[2], wd = scalP[3];
                float att  = 0.001f * hsum / fmaxf(sqrtf(h2), 1e-12f);
                float zt   = (t - 1 < len) ? fmaxf(att, 0.f) : 0.f;
                float gate = sigmoidf_(li + wd + blgr);
                float ns   = tanhf(outP[300 + ei] + bti + gate * outP[400 + ei] + bts);
                sreg = (1.f - zt) * sreg + zt * ns;
                ssP[ei] = sreg;
                __nv_bfloat16 sh = __float2bfloat16(sreg);
                sbHiP[ei] = sh;
                sbLoP[ei] = __float2bfloat16(sreg - __bfloat162float(sh));
            }
        }
        __syncthreads();
    }

    if (tid < NC_) {
        float a = b_out[tid];
        for (int k = 0; k < 100; ++k)
            a = fmaf(W_out[tid * 100 + k], ss0[k], a);
        out[b0g * NC_ + tid] = a;
    } else if (tid >= 32 && tid < 32 + NC_) {
        int c = tid - 32;
        float a = b_out[c];
        for (int k = 0; k < 100; ++k)
            a = fmaf(W_out[c * 100 + k], ss1[k], a);
        out[(b0g + 1) * NC_ + c] = a;
    }
}

extern "C" void kernel_launch(void* const* d_in, const int* in_sizes, int n_in,
                              void* d_out, int out_size)
{
    const int*   txt   = (const int*)  d_in[0];
    const int*   lens  = (const int*)  d_in[1];
    const float* emb   = (const float*)d_in[2];
    const float* W_ih  = (const float*)d_in[3];
    const float* W_hh  = (const float*)d_in[4];
    const float* b_ih  = (const float*)d_in[5];
    const float* b_hh  = (const float*)d_in[6];
    const float* W_lgr = (const float*)d_in[7];
    const float* b_lgr = (const float*)d_in[8];
    const float* W_ts  = (const float*)d_in[9];
    const float* b_ts  = (const float*)d_in[10];
    const float* W_ti  = (const float*)d_in[11];
    const float* b_ti  = (const float*)d_in[12];
    const float* W_out = (const float*)d_in[13];
    const float* b_out = (const float*)d_in[14];
    float* out = (float*)d_out;

    cudaFuncSetAttribute(xp_kernel,
                         cudaFuncAttributeMaxDynamicSharedMemorySize,
                         A_SMEM_BYTES);
    cudaFuncSetAttribute(scan_kernel,
                         cudaFuncAttributeMaxDynamicSharedMemorySize,
                         SC_SMEM_BYTES);

    cvt_emb_kernel<<<(NT_ * E_ / 4 + 255) / 256, 256>>>(emb);
    norm_kernel<<<(NT_ * 32 + 255) / 256, 256>>>(emb);
    cvt_w_kernel<<<(NP_ * KP_ + 255) / 256, 256>>>(W_ih);
    cvt_ws_kernel<<<(512 * 112 + 255) / 256, 256>>>(W_hh, W_ti, W_ts);

    xp_kernel<<<(B_ * T_ / 128) * 2, 256, A_SMEM_BYTES>>>(txt, b_ih);
    scan_kernel<<<B_ / 2, 256, SC_SMEM_BYTES>>>(lens,
                                 b_hh, W_lgr, b_lgr, b_ts, b_ti,
                                 W_out, b_out, out);
}